// round 2
// baseline (speedup 1.0000x reference)
#include <cuda_runtime.h>
#include <math.h>

// ---------------------------------------------------------------------------
// 16-qubit statevector simulator, batch 512.
// Index-bit convention: circuit qubit i  <->  linear-index bit (15 - i).
// Layer = [U on all 16 bits] then CNOT ladder: (b15->b14)...(b1->b0), (b0->b15)
//   (amplitude at index i moves to f(i); ladder = suffix-XOR of index bits).
// Pass A: gates on bits 8..15 + suffix-XOR perm on bits 8..15 (folded in store)
// Pass B: gates on bits 0..7 + CNOT(b8->b7) + suffix-XOR on bits 0..7 seeded
//         by b8 + CNOT(b0'->b15)  (perm folded into gather-store / final sign)
// ---------------------------------------------------------------------------

#define NSTATE 65536
#define BATCHN 512
#define TPB    512
#define TILE   8192

__device__ float g_re[(size_t)BATCHN * NSTATE];
__device__ float g_im[(size_t)BATCHN * NSTATE];

// U = Ry(p2) * Rx(p1) * Rz(p0), stored as 8 floats: u00r,u00i,u01r,u01i,u10r,u10i,u11r,u11i
__device__ __forceinline__ void compute_gate(const float* __restrict__ par,
                                             int layer, int cq, float* uo) {
    const float* pp = par + ((layer * 16 + cq) * 3);
    float sz, cz, sx, cx_, sy, cy;
    sincosf(0.5f * pp[0], &sz, &cz);
    sincosf(0.5f * pp[1], &sx, &cx_);
    sincosf(0.5f * pp[2], &sy, &cy);
    // M = Rx * Rz,  Rz = diag(e0, e1), e0 = (cz,-sz), e1 = (cz,sz)
    float M00r =  cx_ * cz, M00i = -cx_ * sz;
    float M01r =  sx  * sz, M01i = -sx  * cz;
    float M10r = -sx  * sz, M10i = -sx  * cz;
    float M11r =  cx_ * cz, M11i =  cx_ * sz;
    // U = Ry * M
    uo[0] = cy * M00r - sy * M10r;  uo[1] = cy * M00i - sy * M10i;
    uo[2] = cy * M01r - sy * M11r;  uo[3] = cy * M01i - sy * M11i;
    uo[4] = sy * M00r + cy * M10r;  uo[5] = sy * M00i + cy * M10i;
    uo[6] = sy * M01r + cy * M11r;  uo[7] = sy * M01i + cy * M11i;
}

__device__ __forceinline__ void apply2(float* __restrict__ sre, float* __restrict__ sim,
                                       int i0, int i1, const float* u) {
    float ar = sre[i0], ai = sim[i0];
    float br = sre[i1], bi = sim[i1];
    sre[i0] = u[0]*ar - u[1]*ai + u[2]*br - u[3]*bi;
    sim[i0] = u[0]*ai + u[1]*ar + u[2]*bi + u[3]*br;
    sre[i1] = u[4]*ar - u[5]*ai + u[6]*br - u[7]*bi;
    sim[i1] = u[4]*ai + u[5]*ar + u[6]*bi + u[7]*br;
}

// suffix-xor over 8 bits: bit k -> xor(bits k..7)
__device__ __forceinline__ int sfx8(int v) {
    v ^= v >> 1; v ^= v >> 2; v ^= v >> 4;
    return v;
}

// ---------------------------------------------------------------------------
// Pass A: tile = bits {0..4} U {8..15}, fixed bits 5..7 = blockIdx.x (c3)
// SMEM index t = (h<<5)|l, h = bits 8..15, l = bits 0..4.
// ---------------------------------------------------------------------------
__global__ void __launch_bounds__(TPB) kA(const float* __restrict__ x,
                                          const float* __restrict__ par,
                                          int layer, int first) {
    extern __shared__ float sm[];
    float* sre = sm;
    float* sim = sm + TILE;
    float* gU  = sm + 2 * TILE;        // 64 floats
    float* pHi = gU + 64;              // 256
    float* pLo = pHi + 256;            // 32
    float* csn = pLo + 32;             // 32

    const int tid = threadIdx.x;
    const int c3  = blockIdx.x;        // bits 5..7
    const int b   = blockIdx.y;
    const size_t base = (size_t)b << 16;

    if (tid < 8) compute_gate(par, layer, 7 - tid, gU + tid * 8);  // bit 8+j -> cq 7-j

    if (first) {
        if (tid < 16) {  // csn[m]=cos(x/2), csn[16+m]=sin(x/2) for bit m (cq 15-m)
            float s, c; sincosf(0.5f * x[b * 16 + (15 - tid)], &s, &c);
            csn[tid] = c; csn[16 + tid] = s;
        }
        __syncthreads();
        if (tid < 256) {
            float pr = 1.f;
            #pragma unroll
            for (int j = 0; j < 8; ++j)
                pr *= ((tid >> j) & 1) ? csn[16 + 8 + j] : csn[8 + j];
            pHi[tid] = pr;
        } else if (tid < 288) {
            int e = tid - 256;
            float pr = 1.f;
            #pragma unroll
            for (int j = 0; j < 5; ++j)
                pr *= ((e >> j) & 1) ? csn[16 + j] : csn[j];
            #pragma unroll
            for (int j = 5; j < 8; ++j)
                pr *= ((c3 >> (j - 5)) & 1) ? csn[16 + j] : csn[j];
            pLo[e] = pr;
        }
        __syncthreads();
        const int pc3 = __popc((unsigned)c3);
        #pragma unroll
        for (int t = tid; t < TILE; t += TPB) {
            int h = t >> 5, l = t & 31;
            float m = pHi[h] * pLo[l];
            int pc = (__popc((unsigned)h) + __popc((unsigned)l) + pc3) & 3;
            float re = 0.f, im = 0.f;
            if (pc == 0) re = m; else if (pc == 1) im = -m;
            else if (pc == 2) re = -m; else im = m;
            sre[t] = re; sim[t] = im;
        }
    } else {
        #pragma unroll
        for (int t = tid; t < TILE; t += TPB) {
            int h = t >> 5, l = t & 31;
            size_t g = base + ((size_t)h << 8) + (c3 << 5) + l;
            sre[t] = g_re[g]; sim[t] = g_im[g];
        }
    }
    __syncthreads();

    // gates on bits 8..15 (pairs stride 32<<j in SMEM; lanes vary l -> no conflicts)
    #pragma unroll
    for (int j = 0; j < 8; ++j) {
        float u[8];
        #pragma unroll
        for (int k = 0; k < 8; ++k) u[k] = gU[j * 8 + k];
        #pragma unroll
        for (int pp = 0; pp < 4096; pp += TPB) {
            int p = pp + tid;
            int l = p & 31, hp = p >> 5;
            int h0 = ((hp >> j) << (j + 1)) | (hp & ((1 << j) - 1));
            int i0 = (h0 << 5) | l;
            apply2(sre, sim, i0, i0 | (32 << j), u);
        }
        __syncthreads();
    }

    // store; CNOT ladder on bits 8..15 folded into destination address
    // (h' = suffix-xor(h); per-warp h is constant -> stays coalesced)
    #pragma unroll
    for (int t = tid; t < TILE; t += TPB) {
        int h = t >> 5, l = t & 31;
        int v = sfx8(h);
        size_t g = base + ((size_t)v << 8) + (c3 << 5) + l;
        g_re[g] = sre[t]; g_im[g] = sim[t];
    }
}

// ---------------------------------------------------------------------------
// Pass B (mid layers): tile = bits {0..11} U {15}, fixed bits 12..14 = cc
// SMEM index t = (b15<<12) | low12.
// ---------------------------------------------------------------------------
__global__ void __launch_bounds__(TPB) kBmid(const float* __restrict__ par, int layer) {
    extern __shared__ float sm[];
    float* sre = sm;
    float* sim = sm + TILE;
    float* gU  = sm + 2 * TILE;

    const int tid = threadIdx.x;
    const int cc  = blockIdx.x;        // bits 12..14
    const int b   = blockIdx.y;
    const size_t base = (size_t)b << 16;

    if (tid < 8) compute_gate(par, layer, 15 - tid, gU + tid * 8);  // bit q -> cq 15-q

    #pragma unroll
    for (int t = tid; t < TILE; t += TPB) {
        int b15 = t >> 12, lo = t & 4095;
        size_t g = base + ((size_t)b15 << 15) + (cc << 12) + lo;
        sre[t] = g_re[g]; sim[t] = g_im[g];
    }
    __syncthreads();

    #pragma unroll
    for (int q = 0; q < 8; ++q) {
        float u[8];
        #pragma unroll
        for (int k = 0; k < 8; ++k) u[k] = gU[q * 8 + k];
        #pragma unroll
        for (int pp = 0; pp < 4096; pp += TPB) {
            int p = pp + tid;
            int pl = p & 2047, b15p = p >> 11;
            int i0 = (b15p << 12) | (((pl >> q) << (q + 1)) | (pl & ((1 << q) - 1)));
            apply2(sre, sim, i0, i0 | (1 << q), u);
        }
        __syncthreads();
    }

    // store with ladder-permutation folded in as a gather:
    // dst low8 d = sfx8(v) ^ (b8?0xFF:0) ; b15_dst = b15_src ^ d0
    // inverse: v = (d^mask) ^ ((d^mask)>>1), b15_src = b15_dst ^ d0
    #pragma unroll
    for (int t = tid; t < TILE; t += TPB) {
        int lo = t & 4095, b15d = t >> 12;
        int u8 = (lo & 255) ^ (((lo >> 8) & 1) ? 255 : 0);
        int vsrc = u8 ^ (u8 >> 1);
        int b15s = b15d ^ (t & 1);
        int src = (b15s << 12) | (lo & 0xF00) | vsrc;
        size_t g = base + ((size_t)b15d << 15) + (cc << 12) + lo;
        g_re[g] = sre[src]; g_im[g] = sim[src];
    }
}

// ---------------------------------------------------------------------------
// Pass B final: one CTA per batch element, loops cc=0..7, computes <Z_i>.
// Permutation never materialized: final index bits used directly for signs.
// ---------------------------------------------------------------------------
__global__ void __launch_bounds__(TPB) kBlast(const float* __restrict__ par, int layer,
                                              float* __restrict__ out) {
    extern __shared__ float sm[];
    float* sre = sm;
    float* sim = sm + TILE;
    float* gU  = sm + 2 * TILE;

    const int tid = threadIdx.x;
    const int b   = blockIdx.x;
    const size_t base = (size_t)b << 16;

    if (tid < 8) compute_gate(par, layer, 15 - tid, gU + tid * 8);

    float acc[16];
    #pragma unroll
    for (int m = 0; m < 16; ++m) acc[m] = 0.f;

    for (int cc = 0; cc < 8; ++cc) {
        __syncthreads();  // gU visible (iter 0); SMEM reuse safe (iters 1..7)
        #pragma unroll
        for (int t = tid; t < TILE; t += TPB) {
            int b15 = t >> 12, lo = t & 4095;
            size_t g = base + ((size_t)b15 << 15) + (cc << 12) + lo;
            sre[t] = g_re[g]; sim[t] = g_im[g];
        }
        __syncthreads();

        #pragma unroll
        for (int q = 0; q < 8; ++q) {
            float u[8];
            #pragma unroll
            for (int k = 0; k < 8; ++k) u[k] = gU[q * 8 + k];
            #pragma unroll
            for (int pp = 0; pp < 4096; pp += TPB) {
                int p = pp + tid;
                int pl = p & 2047, b15p = p >> 11;
                int i0 = (b15p << 12) | (((pl >> q) << (q + 1)) | (pl & ((1 << q) - 1)));
                apply2(sre, sim, i0, i0 | (1 << q), u);
            }
            __syncthreads();
        }

        #pragma unroll
        for (int t = tid; t < TILE; t += TPB) {
            float re = sre[t], im = sim[t];
            float p = re * re + im * im;
            int lo = t & 4095, b15 = t >> 12;
            int d = sfx8(lo & 255) ^ (((lo >> 8) & 1) ? 255 : 0);
            int b15f = b15 ^ (d & 1);
            int full = (b15f << 15) | (cc << 12) | (lo & 0xF00) | d;
            #pragma unroll
            for (int m = 0; m < 16; ++m)
                acc[m] += ((full >> m) & 1) ? -p : p;
        }
    }
    __syncthreads();

    // reduce 512 threads x 16 values
    const int lane = tid & 31, wrp = tid >> 5;
    #pragma unroll
    for (int m = 0; m < 16; ++m) {
        float v = acc[m];
        #pragma unroll
        for (int o = 16; o > 0; o >>= 1) v += __shfl_xor_sync(0xffffffffu, v, o);
        if (lane == 0) sre[m * 16 + wrp] = v;
    }
    __syncthreads();
    if (tid < 16) {
        float s = 0.f;
        #pragma unroll
        for (int k = 0; k < 16; ++k) s += sre[tid * 16 + k];
        out[b * 16 + (15 - tid)] = s;   // bit m -> circuit qubit 15-m
    }
}

// ---------------------------------------------------------------------------
extern "C" void kernel_launch(void* const* d_in, const int* in_sizes, int n_in,
                              void* d_out, int out_size) {
    const float* x   = (const float*)d_in[0];
    const float* par = (const float*)d_in[1];
    if (n_in >= 2 && in_sizes[0] == 192) {  // robustness to input ordering
        const float* t = x; x = par; par = t;
    }
    float* out = (float*)d_out;

    const size_t smA = (size_t)(2 * TILE + 64 + 256 + 32 + 32) * sizeof(float);
    const size_t smB = (size_t)(2 * TILE + 64) * sizeof(float);

    cudaFuncSetAttribute(kA,     cudaFuncAttributeMaxDynamicSharedMemorySize, (int)smA);
    cudaFuncSetAttribute(kBmid,  cudaFuncAttributeMaxDynamicSharedMemorySize, (int)smB);
    cudaFuncSetAttribute(kBlast, cudaFuncAttributeMaxDynamicSharedMemorySize, (int)smB);

    dim3 grid8(8, BATCHN);
    for (int layer = 0; layer < 4; ++layer) {
        kA<<<grid8, TPB, smA>>>(x, par, layer, layer == 0 ? 1 : 0);
        if (layer < 3) kBmid<<<grid8, TPB, smB>>>(par, layer);
        else           kBlast<<<BATCHN, TPB, smB>>>(par, layer, out);
    }
}

// round 3
// speedup vs baseline: 1.4856x; 1.4856x over previous
#include <cuda_runtime.h>
#include <math.h>

// ---------------------------------------------------------------------------
// 16-qubit statevector simulator, batch 512 — register/shuffle version.
// Index-bit convention: circuit qubit i <-> linear-index bit (15 - i).
// Layer = [1q gates on all bits] then CNOT ladder = suffix-XOR permutation.
// Pass A: gates bits 8..15 + suffix-xor perm on bits 8..15 (in-register).
// Pass B: gates bits 0..7 + perm: d = sfx8(v) ^ (b8?0xFF:0), b15 ^= d0.
// Warp = 9 bits: lane = 5 low gate bits, 4 register bits (16 amps/thread).
// Gates on 3 reg bits: pure FFMA. Gates on 5 lane bits: shfl_xor butterfly.
// Perm: per-dest-slot single shuffle (src slot compile-time, src lane runtime).
// ---------------------------------------------------------------------------

#define TPB 512
#define NST 65536
#define BAT 512

__device__ float2 g_st[(size_t)BAT * NST];
__device__ float  g_part[BAT * 8 * 16];

// U = Ry(p2)*Rx(p1)*Rz(p0): 8 floats u00r,u00i,u01r,u01i,u10r,u10i,u11r,u11i
__device__ __forceinline__ void compute_gate(const float* __restrict__ par,
                                             int layer, int cq, float* uo) {
    const float* pp = par + ((layer * 16 + cq) * 3);
    float sz, cz, sx, cx_, sy, cy;
    sincosf(0.5f * pp[0], &sz, &cz);
    sincosf(0.5f * pp[1], &sx, &cx_);
    sincosf(0.5f * pp[2], &sy, &cy);
    float M00r =  cx_ * cz, M00i = -cx_ * sz;
    float M01r =  sx  * sz, M01i = -sx  * cz;
    float M10r = -sx  * sz, M10i = -sx  * cz;
    float M11r =  cx_ * cz, M11i =  cx_ * sz;
    uo[0] = cy * M00r - sy * M10r;  uo[1] = cy * M00i - sy * M10i;
    uo[2] = cy * M01r - sy * M11r;  uo[3] = cy * M01i - sy * M11i;
    uo[4] = sy * M00r + cy * M10r;  uo[5] = sy * M00i + cy * M10i;
    uo[6] = sy * M01r + cy * M11r;  uo[7] = sy * M01i + cy * M11i;
}

// gate on register bit B (pairs (s, s|B)), pure FFMA
template<int B>
__device__ __forceinline__ void rgate(float* re, float* im, const float* __restrict__ u) {
    const float u0=u[0],u1=u[1],u2=u[2],u3=u[3],u4=u[4],u5=u[5],u6=u[6],u7=u[7];
    #pragma unroll
    for (int s = 0; s < 16; ++s) if (!(s & B)) {
        float ar=re[s],   ai=im[s];
        float br=re[s|B], bi=im[s|B];
        re[s]   = u0*ar - u1*ai + u2*br - u3*bi;
        im[s]   = u0*ai + u1*ar + u2*bi + u3*br;
        re[s|B] = u4*ar - u5*ai + u6*br - u7*bi;
        im[s|B] = u4*ai + u5*ar + u6*bi + u7*br;
    }
}

// gate on lane bit j: butterfly via shfl_xor
__device__ __forceinline__ void lgate(float* re, float* im, const float* __restrict__ u,
                                      int lane, int j) {
    const int hi = (lane >> j) & 1;
    const float car = hi ? u[6] : u[0], cai = hi ? u[7] : u[1];   // own
    const float cbr = hi ? u[4] : u[2], cbi = hi ? u[5] : u[3];   // partner
    #pragma unroll
    for (int s = 0; s < 16; ++s) {
        float pr = __shfl_xor_sync(0xffffffffu, re[s], 1 << j);
        float pi = __shfl_xor_sync(0xffffffffu, im[s], 1 << j);
        float nr = car*re[s] - cai*im[s] + cbr*pr - cbi*pi;
        float ni = car*im[s] + cai*re[s] + cbr*pi + cbi*pr;
        re[s] = nr; im[s] = ni;
    }
}

// ---------------------------------------------------------------------------
// Pass A: tile bits {0..4} U {8..15}, c3 = bits 5..7.  Lane = h bits 0..4
// (index bits 8..12), reg slot = (l0<<3)|h57 (h57 = index bits 13..15).
// SMEM tile float2[8192], swizzled: pos = h*32 + (l ^ (h & 30)).
// ---------------------------------------------------------------------------
__global__ void __launch_bounds__(TPB) kA(const float* __restrict__ x,
                                          const float* __restrict__ par,
                                          int layer, int first) {
    extern __shared__ float2 tile[];            // 8192 float2 = 64KB
    float* gU  = (float*)(tile + 8192);         // 64
    float* pHi = gU + 64;                       // 256
    float* pLo = pHi + 256;                     // 32
    float* csn = pLo + 32;                      // 32

    const int tid = threadIdx.x, lane = tid & 31, w = tid >> 5;
    const int c3  = blockIdx.x;
    const unsigned base = (unsigned)blockIdx.y << 16;

    if (tid < 8) compute_gate(par, layer, 7 - tid, gU + tid * 8); // bit 8+j -> cq 7-j

    if (first) {
        if (tid < 16) {
            float s, c; sincosf(0.5f * x[blockIdx.y * 16 + (15 - tid)], &s, &c);
            csn[tid] = c; csn[16 + tid] = s;
        }
        __syncthreads();
        if (tid < 256) {
            float pr = 1.f;
            #pragma unroll
            for (int j = 0; j < 8; ++j)
                pr *= ((tid >> j) & 1) ? csn[16 + 8 + j] : csn[8 + j];
            pHi[tid] = pr;
        } else if (tid < 288) {
            int e = tid - 256;
            float pr = 1.f;
            #pragma unroll
            for (int j = 0; j < 5; ++j)
                pr *= ((e >> j) & 1) ? csn[16 + j] : csn[j];
            #pragma unroll
            for (int j = 5; j < 8; ++j)
                pr *= ((c3 >> (j - 5)) & 1) ? csn[16 + j] : csn[j];
            pLo[e] = pr;
        }
        __syncthreads();
        const int pc3 = __popc((unsigned)c3);
        #pragma unroll
        for (int t = tid; t < 8192; t += TPB) {
            int h = t >> 5, l = t & 31;
            float m = pHi[h] * pLo[l];
            int pc = (__popc((unsigned)h) + __popc((unsigned)l) + pc3) & 3;
            float re = 0.f, im = 0.f;
            if (pc == 0) re = m; else if (pc == 1) im = -m;
            else if (pc == 2) re = -m; else im = m;
            tile[h * 32 + (l ^ (h & 30))] = make_float2(re, im);
        }
    } else {
        #pragma unroll
        for (int t = tid; t < 8192; t += TPB) {
            int h = t >> 5, l = t & 31;
            tile[h * 32 + (l ^ (h & 30))] = g_st[base + (h << 8) + (c3 << 5) + l];
        }
    }
    __syncthreads();

    // transpose-read into registers (warp w owns columns l = 2w, 2w+1)
    float re[16], im[16];
    #pragma unroll
    for (int h57 = 0; h57 < 8; ++h57) {
        int h = (h57 << 5) | lane;
        float4 v = *(const float4*)(tile + (h * 32 + ((w * 2) ^ (h & 30))));
        re[h57] = v.x; im[h57] = v.y; re[8 | h57] = v.z; im[8 | h57] = v.w;
    }

    // gates: reg bits (index bits 13,14,15 = gU[5..7]), lane bits (8..12 = gU[0..4])
    rgate<1>(re, im, gU + 5 * 8);
    rgate<2>(re, im, gU + 6 * 8);
    rgate<4>(re, im, gU + 7 * 8);
    #pragma unroll
    for (int j = 0; j < 5; ++j) lgate(re, im, gU + j * 8, lane, j);

    // perm: dest d = sfx8(h_src) <=> src h = d ^ (d>>1)
    float nr[16], ni[16];
    #pragma unroll
    for (int d57 = 0; d57 < 8; ++d57) {
        const int v57 = d57 ^ (d57 >> 1);                 // compile-time src slot bits
        const int u   = ((d57 & 1) << 5) | lane;
        const int sl  = (u ^ (u >> 1)) & 31;              // runtime src lane
        nr[d57]     = __shfl_sync(0xffffffffu, re[v57],     sl);
        ni[d57]     = __shfl_sync(0xffffffffu, im[v57],     sl);
        nr[8 | d57] = __shfl_sync(0xffffffffu, re[8 | v57], sl);
        ni[8 | d57] = __shfl_sync(0xffffffffu, im[8 | v57], sl);
    }

    // store-transpose (own columns only — no sync needed before)
    #pragma unroll
    for (int d57 = 0; d57 < 8; ++d57) {
        int d = (d57 << 5) | lane;
        *(float4*)(tile + (d * 32 + ((w * 2) ^ (d & 30)))) =
            make_float4(nr[d57], ni[d57], nr[8 | d57], ni[8 | d57]);
    }
    __syncthreads();

    #pragma unroll
    for (int t = tid; t < 8192; t += TPB) {
        int h = t >> 5, l = t & 31;
        g_st[base + (h << 8) + (c3 << 5) + l] = tile[h * 32 + (l ^ (h & 30))];
    }
}

// ---------------------------------------------------------------------------
// Pass B common: warp = bits 0..8 (lane = bits 0..4, slot = (b8<<3)|bits5..7),
// warp id w: b15 = w>>3, w9 = w&7 -> bits 9..11;  cc = bits 12..14 (grid).
// ---------------------------------------------------------------------------
__device__ __forceinline__ void bload(float* re, float* im, unsigned base,
                                      int b15, int cc, int w9, int lane) {
    #pragma unroll
    for (int s = 0; s < 16; ++s) {
        unsigned g = base + ((unsigned)b15 << 15) + (cc << 12) + (w9 << 9)
                   + ((s >> 3) << 8) + ((s & 7) << 5) + lane;
        float2 v = g_st[g];
        re[s] = v.x; im[s] = v.y;
    }
}

__device__ __forceinline__ void bgates(float* re, float* im, const float* gU, int lane) {
    rgate<1>(re, im, gU + 5 * 8);   // bit 5
    rgate<2>(re, im, gU + 6 * 8);   // bit 6
    rgate<4>(re, im, gU + 7 * 8);   // bit 7
    #pragma unroll
    for (int j = 0; j < 5; ++j) lgate(re, im, gU + j * 8, lane, j);
}

// perm gather: dest (d, b8) from src v = u8 ^ (u8>>1), u8 = d ^ (b8?255:0)
__device__ __forceinline__ void bperm(const float* re, const float* im,
                                      float* nr, float* ni, int lane) {
    #pragma unroll
    for (int sd = 0; sd < 16; ++sd) {
        const int b8  = sd >> 3, dhi = sd & 7;
        const int e   = dhi ^ (b8 ? 7 : 0);
        const int v57 = e ^ (e >> 1);                    // compile-time
        const int ss  = (b8 << 3) | v57;                 // compile-time src slot
        const int ul  = (((dhi & 1) << 5) | lane) ^ (b8 ? 63 : 0);
        const int sl  = (ul ^ (ul >> 1)) & 31;           // runtime src lane
        nr[sd] = __shfl_sync(0xffffffffu, re[ss], sl);
        ni[sd] = __shfl_sync(0xffffffffu, im[ss], sl);
    }
}

__global__ void __launch_bounds__(TPB) kBmid(const float* __restrict__ par, int layer) {
    __shared__ float  gU[64];
    __shared__ float2 xbuf[2][8][16][16];   // 32KB: b15-flip exchange (odd lanes)

    const int tid = threadIdx.x, lane = tid & 31, w = tid >> 5;
    const int b15 = w >> 3, w9 = w & 7;
    const int cc  = blockIdx.x;
    const unsigned base = (unsigned)blockIdx.y << 16;

    if (tid < 8) compute_gate(par, layer, 15 - tid, gU + tid * 8); // bit q -> cq 15-q

    float re[16], im[16];
    bload(re, im, base, b15, cc, w9, lane);
    __syncthreads();                         // gU visible

    bgates(re, im, gU, lane);

    float nr[16], ni[16];
    bperm(re, im, nr, ni, lane);

    // b15 flip (b15_dst = b15_src ^ d0): odd dest lanes swap with partner warp w^8
    if (lane & 1) {
        #pragma unroll
        for (int s = 0; s < 16; ++s)
            xbuf[b15][w9][s][lane >> 1] = make_float2(nr[s], ni[s]);
    }
    __syncthreads();
    if (lane & 1) {
        #pragma unroll
        for (int s = 0; s < 16; ++s) {
            float2 v = xbuf[b15 ^ 1][w9][s][lane >> 1];
            nr[s] = v.x; ni[s] = v.y;
        }
    }

    #pragma unroll
    for (int s = 0; s < 16; ++s) {
        unsigned g = base + ((unsigned)b15 << 15) + (cc << 12) + (w9 << 9)
                   + ((s >> 3) << 8) + ((s & 7) << 5) + lane;
        g_st[g] = make_float2(nr[s], ni[s]);
    }
}

// ---------------------------------------------------------------------------
// Final pass B: per (cc, batch) CTA; Walsh-tree <Z> partials (deterministic).
// ---------------------------------------------------------------------------
__global__ void __launch_bounds__(TPB) kBlast(const float* __restrict__ par, int layer) {
    __shared__ float gU[64];
    __shared__ float red[16][17];

    const int tid = threadIdx.x, lane = tid & 31, w = tid >> 5;
    const int b15 = w >> 3, w9 = w & 7;
    const int cc  = blockIdx.x;
    const unsigned base = (unsigned)blockIdx.y << 16;

    if (tid < 8) compute_gate(par, layer, 15 - tid, gU + tid * 8);

    float re[16], im[16];
    bload(re, im, base, b15, cc, w9, lane);
    __syncthreads();

    bgates(re, im, gU, lane);

    float nr[16], ni[16];
    bperm(re, im, nr, ni, lane);

    // probabilities per dest slot; slot bits: s0..s2 = d5..d7, s3 = b8
    float p[16];
    #pragma unroll
    for (int s = 0; s < 16; ++s) p[s] = nr[s] * nr[s] + ni[s] * ni[s];

    float ee[8], T8 = 0.f;
    #pragma unroll
    for (int k = 0; k < 8; ++k) { ee[k] = p[k] + p[k + 8]; T8 += p[k] - p[k + 8]; }
    float a0 = ee[0] + ee[4], a1 = ee[1] + ee[5], a2 = ee[2] + ee[6], a3 = ee[3] + ee[7];
    float T7 = (ee[0] - ee[4]) + (ee[1] - ee[5]) + (ee[2] - ee[6]) + (ee[3] - ee[7]);
    float c0 = a0 + a2, c1 = a1 + a3;
    float T6 = (a0 - a2) + (a1 - a3);
    float T0 = c0 + c1, T5 = c0 - c1;

    // thread-constant destination bits: 0..4 = lane, 9..11 = w9, 12..14 = cc,
    // 15 = b15 ^ d0 (d0 = lane bit 0)
    const int bitsv = ((b15 ^ (lane & 1)) << 15) | (cc << 12) | (w9 << 9) | lane;
    float acc[16];
    #pragma unroll
    for (int m = 0; m < 16; ++m) {
        if      (m == 5) acc[m] = T5;
        else if (m == 6) acc[m] = T6;
        else if (m == 7) acc[m] = T7;
        else if (m == 8) acc[m] = T8;
        else             acc[m] = ((bitsv >> m) & 1) ? -T0 : T0;
    }

    #pragma unroll
    for (int m = 0; m < 16; ++m) {
        float v = acc[m];
        #pragma unroll
        for (int o = 16; o > 0; o >>= 1) v += __shfl_xor_sync(0xffffffffu, v, o);
        if (lane == 0) red[m][w] = v;
    }
    __syncthreads();
    if (tid < 16) {
        float s = 0.f;
        #pragma unroll
        for (int k = 0; k < 16; ++k) s += red[tid][k];
        g_part[(blockIdx.y * 8 + cc) * 16 + tid] = s;
    }
}

__global__ void kBfin(float* __restrict__ out) {
    int i = blockIdx.x * blockDim.x + threadIdx.x;
    if (i < BAT * 16) {
        int b = i >> 4, m = i & 15;
        float s = 0.f;
        #pragma unroll
        for (int cc = 0; cc < 8; ++cc) s += g_part[(b * 8 + cc) * 16 + m];
        out[b * 16 + (15 - m)] = s;      // bit m -> circuit qubit 15-m
    }
}

// ---------------------------------------------------------------------------
extern "C" void kernel_launch(void* const* d_in, const int* in_sizes, int n_in,
                              void* d_out, int out_size) {
    const float* x   = (const float*)d_in[0];
    const float* par = (const float*)d_in[1];
    if (n_in >= 2 && in_sizes[0] == 192) {
        const float* t = x; x = par; par = t;
    }
    float* out = (float*)d_out;

    const size_t smA = 8192 * sizeof(float2) + (64 + 256 + 32 + 32) * sizeof(float);
    cudaFuncSetAttribute(kA, cudaFuncAttributeMaxDynamicSharedMemorySize, (int)smA);

    dim3 grid8(8, BAT);
    for (int layer = 0; layer < 4; ++layer) {
        kA<<<grid8, TPB, smA>>>(x, par, layer, layer == 0 ? 1 : 0);
        if (layer < 3) {
            kBmid<<<grid8, TPB>>>(par, layer);
        } else {
            kBlast<<<grid8, TPB>>>(par, layer);
            kBfin<<<32, 256>>>(out);
        }
    }
}

// round 4
// speedup vs baseline: 1.9112x; 1.2865x over previous
#include <cuda_runtime.h>
#include <math.h>

// ---------------------------------------------------------------------------
// 16-qubit statevector, batch 512. circuit qubit i <-> index bit (15-i).
// Layer = 16 one-qubit gates + CNOT-ladder = suffix-XOR permutation.
// Pass A: gates bits 8..15 (two all-rgate stages + 1 SMEM exchange),
//         perm on bits 8..15 folded into store address.
// Pass B: gates bits 0..7 (3 packed rgates + 5 packed lane-gates),
//         perm via in-place register cycles + b15 exchange through SMEM.
// f32x2 packed FMA: two amps packed along a never-gated bit per section.
// ---------------------------------------------------------------------------

#define TPB 512
#define BAT 512

typedef unsigned long long u64;

__device__ float2 g_st[(size_t)BAT * 65536];
__device__ float  g_part[BAT * 8 * 16];

// ---------------- packed f32x2 helpers ----------------
__device__ __forceinline__ u64 pk2(float x, float y) {
    u64 r; asm("mov.b64 %0,{%1,%2};" : "=l"(r) : "f"(x), "f"(y)); return r;
}
__device__ __forceinline__ void upk2(u64 v, float& x, float& y) {
    asm("mov.b64 {%0,%1},%2;" : "=f"(x), "=f"(y) : "l"(v));
}
__device__ __forceinline__ u64 bc2(float x) { return pk2(x, x); }
__device__ __forceinline__ u64 f2mul(u64 a, u64 b) {
    u64 r; asm("mul.rn.f32x2 %0,%1,%2;" : "=l"(r) : "l"(a), "l"(b)); return r;
}
__device__ __forceinline__ u64 f2fma(u64 a, u64 b, u64 c) {
    u64 r; asm("fma.rn.f32x2 %0,%1,%2,%3;" : "=l"(r) : "l"(a), "l"(b), "l"(c)); return r;
}
__device__ __forceinline__ u64 shfl2x(u64 v, int m) {
    float x, y; upk2(v, x, y);
    x = __shfl_xor_sync(0xffffffffu, x, m);
    y = __shfl_xor_sync(0xffffffffu, y, m);
    return pk2(x, y);
}

// U = Ry(p2)*Rx(p1)*Rz(p0): u00r,u00i,u01r,u01i,u10r,u10i,u11r,u11i
__device__ __forceinline__ void compute_gate(const float* __restrict__ par,
                                             int layer, int cq, float* uo) {
    const float* pp = par + ((layer * 16 + cq) * 3);
    float sz, cz, sx, cx_, sy, cy;
    sincosf(0.5f * pp[0], &sz, &cz);
    sincosf(0.5f * pp[1], &sx, &cx_);
    sincosf(0.5f * pp[2], &sy, &cy);
    float M00r =  cx_ * cz, M00i = -cx_ * sz;
    float M01r =  sx  * sz, M01i = -sx  * cz;
    float M10r = -sx  * sz, M10i = -sx  * cz;
    float M11r =  cx_ * cz, M11i =  cx_ * sz;
    uo[0] = cy * M00r - sy * M10r;  uo[1] = cy * M00i - sy * M10i;
    uo[2] = cy * M01r - sy * M11r;  uo[3] = cy * M01i - sy * M11i;
    uo[4] = sy * M00r + cy * M10r;  uo[5] = sy * M00i + cy * M10i;
    uo[6] = sy * M01r + cy * M11r;  uo[7] = sy * M01i + cy * M11i;
}

// packed gate on slot bit B (8 packs = 16 amps), pure f32x2
template<int B>
__device__ __forceinline__ void rgateP(u64* VR, u64* VI, const float* __restrict__ u) {
    const u64 U0 = bc2(u[0]), U1 = bc2(u[1]), N1 = bc2(-u[1]);
    const u64 U2 = bc2(u[2]), U3 = bc2(u[3]), N3 = bc2(-u[3]);
    const u64 U4 = bc2(u[4]), U5 = bc2(u[5]), N5 = bc2(-u[5]);
    const u64 U6 = bc2(u[6]), U7 = bc2(u[7]), N7 = bc2(-u[7]);
    #pragma unroll
    for (int s = 0; s < 8; ++s) if (!(s & B)) {
        u64 ar = VR[s], ai = VI[s], br = VR[s | B], bi = VI[s | B];
        VR[s]     = f2fma(N3, bi, f2fma(U2, br, f2fma(N1, ai, f2mul(U0, ar))));
        VI[s]     = f2fma(U3, br, f2fma(U2, bi, f2fma(U1, ar, f2mul(U0, ai))));
        VR[s | B] = f2fma(N7, bi, f2fma(U6, br, f2fma(N5, ai, f2mul(U4, ar))));
        VI[s | B] = f2fma(U7, br, f2fma(U6, bi, f2fma(U5, ar, f2mul(U4, ai))));
    }
}

// gate on the pack bit itself (pairs = the two halves of each pack), scalar
__device__ __forceinline__ void pgateP(u64* VR, u64* VI, const float* __restrict__ u) {
    #pragma unroll
    for (int s = 0; s < 8; ++s) {
        float ar, br, ai, bi;
        upk2(VR[s], ar, br); upk2(VI[s], ai, bi);
        float nar = u[0]*ar - u[1]*ai + u[2]*br - u[3]*bi;
        float nai = u[0]*ai + u[1]*ar + u[2]*bi + u[3]*br;
        float nbr = u[4]*ar - u[5]*ai + u[6]*br - u[7]*bi;
        float nbi = u[4]*ai + u[5]*ar + u[6]*bi + u[7]*br;
        VR[s] = pk2(nar, nbr); VI[s] = pk2(nai, nbi);
    }
}

// packed gate on lane bit j (shfl butterfly)
__device__ __forceinline__ void lgateP(u64* VR, u64* VI, const float* __restrict__ u,
                                       int lane, int j) {
    const int hi = (lane >> j) & 1;
    const float car = hi ? u[6] : u[0], cai = hi ? u[7] : u[1];
    const float cbr = hi ? u[4] : u[2], cbi = hi ? u[5] : u[3];
    const u64 CAR = bc2(car), CAI = bc2(cai), NAI = bc2(-cai);
    const u64 CBR = bc2(cbr), CBI = bc2(cbi), NBI = bc2(-cbi);
    #pragma unroll
    for (int s = 0; s < 8; ++s) {
        u64 pr = shfl2x(VR[s], 1 << j), pi = shfl2x(VI[s], 1 << j);
        u64 nr = f2fma(NBI, pi, f2fma(CBR, pr, f2fma(NAI, VI[s], f2mul(CAR, VR[s]))));
        u64 ni = f2fma(CBI, pr, f2fma(CBR, pi, f2fma(CAI, VR[s], f2mul(CAR, VI[s]))));
        VR[s] = nr; VI[s] = ni;
    }
}

// in-place pass-B permutation of 16 slots across lanes (cycle-following).
// dest slot sd=(b8<<3)|dhi <- src slot (b8<<3)|v, v=e^(e>>1), e=dhi^(b8?7:0);
// src lane variants by (dhi parity, b8).
__device__ __forceinline__ void perm16(float* v, int se0, int so0, int se1, int so1) {
    const unsigned M = 0xffffffffu; float t;
    v[0] = __shfl_sync(M, v[0], se0);
    v[1] = __shfl_sync(M, v[1], so0);
    t = v[2]; v[2] = __shfl_sync(M, v[3], se0); v[3] = __shfl_sync(M, t, so0);
    t = v[4]; v[4] = __shfl_sync(M, v[6], se0); v[6] = __shfl_sync(M, v[5], se0);
              v[5] = __shfl_sync(M, v[7], so0); v[7] = __shfl_sync(M, t, so0);
    t = v[8];  v[8]  = __shfl_sync(M, v[12], se1); v[12] = __shfl_sync(M, v[10], se1);
               v[10] = __shfl_sync(M, v[15], se1); v[15] = __shfl_sync(M, t, so1);
    t = v[9];  v[9]  = __shfl_sync(M, v[13], so1); v[13] = __shfl_sync(M, v[11], so1);
               v[11] = __shfl_sync(M, v[14], so1); v[14] = __shfl_sync(M, t, se1);
}

// ---------------------------------------------------------------------------
// Pass A: lanes = bits 0..4 (always), c3 = bits 5..7 (grid).
// Stage1: warp w = bits 12..15, slots = bits 8..11 (pack bit = 11).
// Stage2 (after SMEM exchange): warp w = bits 8..11, slots = bits 12..15
//        (pack bit = 15). Perm sfx8 on bits 8..15 folded into store address.
// ---------------------------------------------------------------------------
__global__ void __launch_bounds__(TPB, 2) kA(const float* __restrict__ x,
                                             const float* __restrict__ par,
                                             int layer, int first) {
    extern __shared__ float2 buf[];               // [e8][e12][lane] = 8192 float2
    float* aux = (float*)(buf + 8192);
    float* gU  = aux;         // 64
    float* csn = aux + 64;    // 32
    float* tL  = aux + 96;    // 32
    float* t8  = aux + 128;   // 16
    float* t12 = aux + 144;   // 16

    const int tid = threadIdx.x, lane = tid & 31, w = tid >> 5;
    const int c3  = blockIdx.x;
    const unsigned base = (unsigned)blockIdx.y << 16;

    if (tid < 8) compute_gate(par, layer, 7 - tid, gU + tid * 8);  // bit 8+j -> cq 7-j

    u64 VR[8], VI[8];

    if (first) {
        if (tid < 16) {
            float s, c; sincosf(0.5f * x[blockIdx.y * 16 + (15 - tid)], &s, &c);
            csn[tid] = c; csn[16 + tid] = s;
        }
        __syncthreads();
        if (tid < 32) {
            float p = 1.f;
            #pragma unroll
            for (int j = 0; j < 5; ++j) p *= ((tid >> j) & 1) ? csn[16 + j] : csn[j];
            #pragma unroll
            for (int j = 5; j < 8; ++j) p *= ((c3 >> (j - 5)) & 1) ? csn[16 + j] : csn[j];
            tL[tid] = p;
        } else if (tid < 48) {
            int e = tid - 32; float p = 1.f;
            #pragma unroll
            for (int j = 0; j < 4; ++j) p *= ((e >> j) & 1) ? csn[16 + 8 + j] : csn[8 + j];
            t8[e] = p;
        } else if (tid < 64) {
            int e = tid - 48; float p = 1.f;
            #pragma unroll
            for (int j = 0; j < 4; ++j) p *= ((e >> j) & 1) ? csn[16 + 12 + j] : csn[12 + j];
            t12[e] = p;
        }
        __syncthreads();
        const int pcBase = __popc((unsigned)lane) + __popc((unsigned)c3) + __popc((unsigned)w);
        const float mw = t12[w] * tL[lane];
        #pragma unroll
        for (int k = 0; k < 8; ++k) {
            float r[2], i2[2];
            #pragma unroll
            for (int h = 0; h < 2; ++h) {
                int e8 = (h << 3) | k;
                float m = mw * t8[e8];
                int pc = (pcBase + __popc((unsigned)e8)) & 3;
                float re = 0.f, im = 0.f;
                if (pc == 0) re = m; else if (pc == 1) im = -m;
                else if (pc == 2) re = -m; else im = m;
                r[h] = re; i2[h] = im;
            }
            VR[k] = pk2(r[0], r[1]); VI[k] = pk2(i2[0], i2[1]);
        }
    } else {
        #pragma unroll
        for (int k = 0; k < 8; ++k) {
            unsigned g0 = base | (w << 12) | (k << 8) | (c3 << 5) | lane;
            float2 a = g_st[g0], b = g_st[g0 | (8u << 8)];
            VR[k] = pk2(a.x, b.x); VI[k] = pk2(a.y, b.y);
        }
    }
    __syncthreads();                               // gU (and tables) visible

    // stage1: gates on bits 8,9,10 (slot bits) + bit 11 (pack bit)
    rgateP<1>(VR, VI, gU + 0);
    rgateP<2>(VR, VI, gU + 8);
    rgateP<4>(VR, VI, gU + 16);
    pgateP(VR, VI, gU + 24);

    // exchange: buf[e8][e12=w][lane]
    #pragma unroll
    for (int k = 0; k < 8; ++k) {
        float r0, r1, i0, i1;
        upk2(VR[k], r0, r1); upk2(VI[k], i0, i1);
        buf[(k * 16 + w) * 32 + lane]       = make_float2(r0, i0);
        buf[((8 | k) * 16 + w) * 32 + lane] = make_float2(r1, i1);
    }
    __syncthreads();
    #pragma unroll
    for (int k = 0; k < 8; ++k) {
        float2 a = buf[(w * 16 + k) * 32 + lane];        // e8=w, e12=k
        float2 b = buf[(w * 16 + (8 | k)) * 32 + lane];  // e12=8|k
        VR[k] = pk2(a.x, b.x); VI[k] = pk2(a.y, b.y);
    }

    // stage2: gates on bits 12,13,14 (slot bits) + bit 15 (pack bit)
    rgateP<1>(VR, VI, gU + 32);
    rgateP<2>(VR, VI, gU + 40);
    rgateP<4>(VR, VI, gU + 48);
    pgateP(VR, VI, gU + 56);

    // store with sfx8 perm folded in: d12 = sfx4(e12), d8 = sfx4(w) ^ (par(e12)?15:0)
    int sw = w ^ (w >> 1); sw ^= (sw >> 2);
    const int dwA = sw, dwB = sw ^ 15;
    #pragma unroll
    for (int k = 0; k < 8; ++k) {
        float r0, r1, i0, i1;
        upk2(VR[k], r0, r1); upk2(VI[k], i0, i1);
        #pragma unroll
        for (int h = 0; h < 2; ++h) {
            int e12 = (h << 3) | k;
            int d12 = e12 ^ (e12 >> 1); d12 ^= (d12 >> 2);
            int dw  = (__popc((unsigned)e12) & 1) ? dwB : dwA;
            unsigned g = base | (d12 << 12) | (dw << 8) | (c3 << 5) | lane;
            g_st[g] = make_float2(h ? r1 : r0, h ? i1 : i0);
        }
    }
}

// ---------------------------------------------------------------------------
// Pass B shared pieces: lane = bits 0..4, slot k = bits 5..7, pack = b8,
// warp: b15 = w>>3, w9 = w&7 -> bits 9..11, cc = bits 12..14 (grid).
// ---------------------------------------------------------------------------
__device__ __forceinline__ void b_load_gates(float* re, float* im,
                                             unsigned base, int b15, int cc,
                                             int w9, int lane, const float* gU) {
    u64 VR[8], VI[8];
    #pragma unroll
    for (int k = 0; k < 8; ++k) {
        unsigned g0 = base | ((unsigned)b15 << 15) | (cc << 12) | (w9 << 9)
                    | (k << 5) | lane;
        float2 a = g_st[g0], b = g_st[g0 | 256u];
        VR[k] = pk2(a.x, b.x); VI[k] = pk2(a.y, b.y);
    }
    __syncthreads();                     // gU visible
    rgateP<1>(VR, VI, gU + 5 * 8);
    rgateP<2>(VR, VI, gU + 6 * 8);
    rgateP<4>(VR, VI, gU + 7 * 8);
    #pragma unroll
    for (int j = 0; j < 5; ++j) lgateP(VR, VI, gU + j * 8, lane, j);
    #pragma unroll
    for (int k = 0; k < 8; ++k) {
        upk2(VR[k], re[k], re[8 | k]);
        upk2(VI[k], im[k], im[8 | k]);
    }
}

__device__ __forceinline__ void lane_variants(int lane, int& se0, int& so0,
                                              int& se1, int& so1) {
    se0 = (lane ^ (lane >> 1)) & 31;
    so0 = se0 ^ 16;
    int u1e = lane ^ 63; se1 = (u1e ^ (u1e >> 1)) & 31;
    int u1o = lane ^ 31; so1 = (u1o ^ (u1o >> 1)) & 31;
}

__global__ void __launch_bounds__(TPB, 2) kBmid(const float* __restrict__ par, int layer) {
    __shared__ float  gU[64];
    __shared__ float2 xbuf[2][8][16][16];

    const int tid = threadIdx.x, lane = tid & 31, w = tid >> 5;
    const int b15 = w >> 3, w9 = w & 7;
    const int cc  = blockIdx.x;
    const unsigned base = (unsigned)blockIdx.y << 16;

    if (tid < 8) compute_gate(par, layer, 15 - tid, gU + tid * 8);  // gU[q]: bit q

    float re[16], im[16];
    b_load_gates(re, im, base, b15, cc, w9, lane, gU);

    int se0, so0, se1, so1; lane_variants(lane, se0, so0, se1, so1);
    perm16(re, se0, so0, se1, so1);
    perm16(im, se0, so0, se1, so1);

    // b15 flip for odd dest lanes: swap with partner warp (w ^ 8)
    if (lane & 1) {
        #pragma unroll
        for (int s = 0; s < 16; ++s)
            xbuf[b15][w9][s][lane >> 1] = make_float2(re[s], im[s]);
    }
    __syncthreads();
    if (lane & 1) {
        #pragma unroll
        for (int s = 0; s < 16; ++s) {
            float2 v = xbuf[b15 ^ 1][w9][s][lane >> 1];
            re[s] = v.x; im[s] = v.y;
        }
    }

    #pragma unroll
    for (int s = 0; s < 16; ++s) {
        unsigned g = base | ((unsigned)b15 << 15) | (cc << 12) | (w9 << 9)
                   | ((s >> 3) << 8) | ((s & 7) << 5) | lane;
        g_st[g] = make_float2(re[s], im[s]);
    }
}

// ---------------------------------------------------------------------------
// Final pass B: Walsh-tree <Z> partials, no state store.
// ---------------------------------------------------------------------------
__global__ void __launch_bounds__(TPB, 2) kBlast(const float* __restrict__ par, int layer) {
    __shared__ float gU[64];
    __shared__ float red[16][17];

    const int tid = threadIdx.x, lane = tid & 31, w = tid >> 5;
    const int b15 = w >> 3, w9 = w & 7;
    const int cc  = blockIdx.x;
    const unsigned base = (unsigned)blockIdx.y << 16;

    if (tid < 8) compute_gate(par, layer, 15 - tid, gU + tid * 8);

    float re[16], im[16];
    b_load_gates(re, im, base, b15, cc, w9, lane, gU);

    int se0, so0, se1, so1; lane_variants(lane, se0, so0, se1, so1);
    perm16(re, se0, so0, se1, so1);
    perm16(im, se0, so0, se1, so1);

    float p[16];
    #pragma unroll
    for (int s = 0; s < 16; ++s) p[s] = re[s] * re[s] + im[s] * im[s];

    float ee[8], T8 = 0.f;
    #pragma unroll
    for (int k = 0; k < 8; ++k) { ee[k] = p[k] + p[k + 8]; T8 += p[k] - p[k + 8]; }
    float a0 = ee[0] + ee[4], a1 = ee[1] + ee[5], a2 = ee[2] + ee[6], a3 = ee[3] + ee[7];
    float T7 = (ee[0] - ee[4]) + (ee[1] - ee[5]) + (ee[2] - ee[6]) + (ee[3] - ee[7]);
    float c0 = a0 + a2, c1 = a1 + a3;
    float T6 = (a0 - a2) + (a1 - a3);
    float T0 = c0 + c1, T5 = c0 - c1;

    const int bitsv = ((b15 ^ (lane & 1)) << 15) | (cc << 12) | (w9 << 9) | lane;
    float acc[16];
    #pragma unroll
    for (int m = 0; m < 16; ++m) {
        if      (m == 5) acc[m] = T5;
        else if (m == 6) acc[m] = T6;
        else if (m == 7) acc[m] = T7;
        else if (m == 8) acc[m] = T8;
        else             acc[m] = ((bitsv >> m) & 1) ? -T0 : T0;
    }

    #pragma unroll
    for (int m = 0; m < 16; ++m) {
        float v = acc[m];
        #pragma unroll
        for (int o = 16; o > 0; o >>= 1) v += __shfl_xor_sync(0xffffffffu, v, o);
        if (lane == 0) red[m][w] = v;
    }
    __syncthreads();
    if (tid < 16) {
        float s = 0.f;
        #pragma unroll
        for (int k = 0; k < 16; ++k) s += red[tid][k];
        g_part[(blockIdx.y * 8 + cc) * 16 + tid] = s;
    }
}

__global__ void kBfin(float* __restrict__ out) {
    int i = blockIdx.x * blockDim.x + threadIdx.x;
    if (i < BAT * 16) {
        int b = i >> 4, m = i & 15;
        float s = 0.f;
        #pragma unroll
        for (int cc = 0; cc < 8; ++cc) s += g_part[(b * 8 + cc) * 16 + m];
        out[b * 16 + (15 - m)] = s;
    }
}

// ---------------------------------------------------------------------------
extern "C" void kernel_launch(void* const* d_in, const int* in_sizes, int n_in,
                              void* d_out, int out_size) {
    const float* x   = (const float*)d_in[0];
    const float* par = (const float*)d_in[1];
    if (n_in >= 2 && in_sizes[0] == 192) {
        const float* t = x; x = par; par = t;
    }
    float* out = (float*)d_out;

    const size_t smA = 8192 * sizeof(float2) + 160 * sizeof(float);
    cudaFuncSetAttribute(kA, cudaFuncAttributeMaxDynamicSharedMemorySize, (int)smA);

    dim3 grid8(8, BAT);
    for (int layer = 0; layer < 4; ++layer) {
        kA<<<grid8, TPB, smA>>>(x, par, layer, layer == 0 ? 1 : 0);
        if (layer < 3) {
            kBmid<<<grid8, TPB>>>(par, layer);
        } else {
            kBlast<<<grid8, TPB>>>(par, layer);
            kBfin<<<32, 256>>>(out);
        }
    }
}

// round 5
// speedup vs baseline: 2.0667x; 1.0814x over previous
#include <cuda_runtime.h>
#include <cuda_fp16.h>
#include <math.h>

// ---------------------------------------------------------------------------
// 16-qubit statevector, batch 512. circuit qubit i <-> index bit (15-i).
// Layer = 16 one-qubit gates + CNOT-ladder = suffix-XOR permutation.
// State stored between passes as __half2(re,im) — 4 B/amp (fp32 compute).
// Pass A: gates bits 8..15 (two all-rgate stages + 1 SMEM exchange),
//         perm on bits 8..15 folded into store address.
// Pass B: gates bits 0..7 (3 packed rgates + 5 packed lane-gates),
//         perm via in-place register cycles + b15 exchange through SMEM.
// ---------------------------------------------------------------------------

#define TPB 512
#define BAT 512

typedef unsigned long long u64;

__device__ __half2 g_st[(size_t)BAT * 65536];
__device__ float   g_part[BAT * 8 * 16];

// ---------------- packed f32x2 helpers ----------------
__device__ __forceinline__ u64 pk2(float x, float y) {
    u64 r; asm("mov.b64 %0,{%1,%2};" : "=l"(r) : "f"(x), "f"(y)); return r;
}
__device__ __forceinline__ void upk2(u64 v, float& x, float& y) {
    asm("mov.b64 {%0,%1},%2;" : "=f"(x), "=f"(y) : "l"(v));
}
__device__ __forceinline__ u64 bc2(float x) { return pk2(x, x); }
__device__ __forceinline__ u64 f2mul(u64 a, u64 b) {
    u64 r; asm("mul.rn.f32x2 %0,%1,%2;" : "=l"(r) : "l"(a), "l"(b)); return r;
}
__device__ __forceinline__ u64 f2fma(u64 a, u64 b, u64 c) {
    u64 r; asm("fma.rn.f32x2 %0,%1,%2,%3;" : "=l"(r) : "l"(a), "l"(b), "l"(c)); return r;
}
__device__ __forceinline__ u64 shfl2x(u64 v, int m) {
    float x, y; upk2(v, x, y);
    x = __shfl_xor_sync(0xffffffffu, x, m);
    y = __shfl_xor_sync(0xffffffffu, y, m);
    return pk2(x, y);
}

// half2 <-> float pair
__device__ __forceinline__ void ld_h2(const __half2* p, float& re, float& im) {
    float2 v = __half22float2(*p); re = v.x; im = v.y;
}
__device__ __forceinline__ void st_h2(__half2* p, float re, float im) {
    *p = __floats2half2_rn(re, im);
}

// U = Ry(p2)*Rx(p1)*Rz(p0): u00r,u00i,u01r,u01i,u10r,u10i,u11r,u11i
__device__ __forceinline__ void compute_gate(const float* __restrict__ par,
                                             int layer, int cq, float* uo) {
    const float* pp = par + ((layer * 16 + cq) * 3);
    float sz, cz, sx, cx_, sy, cy;
    sincosf(0.5f * pp[0], &sz, &cz);
    sincosf(0.5f * pp[1], &sx, &cx_);
    sincosf(0.5f * pp[2], &sy, &cy);
    float M00r =  cx_ * cz, M00i = -cx_ * sz;
    float M01r =  sx  * sz, M01i = -sx  * cz;
    float M10r = -sx  * sz, M10i = -sx  * cz;
    float M11r =  cx_ * cz, M11i =  cx_ * sz;
    uo[0] = cy * M00r - sy * M10r;  uo[1] = cy * M00i - sy * M10i;
    uo[2] = cy * M01r - sy * M11r;  uo[3] = cy * M01i - sy * M11i;
    uo[4] = sy * M00r + cy * M10r;  uo[5] = sy * M00i + cy * M10i;
    uo[6] = sy * M01r + cy * M11r;  uo[7] = sy * M01i + cy * M11i;
}

// packed gate on slot bit B (8 packs = 16 amps), pure f32x2
template<int B>
__device__ __forceinline__ void rgateP(u64* VR, u64* VI, const float* __restrict__ u) {
    const u64 U0 = bc2(u[0]), U1 = bc2(u[1]), N1 = bc2(-u[1]);
    const u64 U2 = bc2(u[2]), U3 = bc2(u[3]), N3 = bc2(-u[3]);
    const u64 U4 = bc2(u[4]), U5 = bc2(u[5]), N5 = bc2(-u[5]);
    const u64 U6 = bc2(u[6]), U7 = bc2(u[7]), N7 = bc2(-u[7]);
    #pragma unroll
    for (int s = 0; s < 8; ++s) if (!(s & B)) {
        u64 ar = VR[s], ai = VI[s], br = VR[s | B], bi = VI[s | B];
        VR[s]     = f2fma(N3, bi, f2fma(U2, br, f2fma(N1, ai, f2mul(U0, ar))));
        VI[s]     = f2fma(U3, br, f2fma(U2, bi, f2fma(U1, ar, f2mul(U0, ai))));
        VR[s | B] = f2fma(N7, bi, f2fma(U6, br, f2fma(N5, ai, f2mul(U4, ar))));
        VI[s | B] = f2fma(U7, br, f2fma(U6, bi, f2fma(U5, ar, f2mul(U4, ai))));
    }
}

// gate on the pack bit itself (pairs = the two halves of each pack), scalar
__device__ __forceinline__ void pgateP(u64* VR, u64* VI, const float* __restrict__ u) {
    #pragma unroll
    for (int s = 0; s < 8; ++s) {
        float ar, br, ai, bi;
        upk2(VR[s], ar, br); upk2(VI[s], ai, bi);
        float nar = u[0]*ar - u[1]*ai + u[2]*br - u[3]*bi;
        float nai = u[0]*ai + u[1]*ar + u[2]*bi + u[3]*br;
        float nbr = u[4]*ar - u[5]*ai + u[6]*br - u[7]*bi;
        float nbi = u[4]*ai + u[5]*ar + u[6]*bi + u[7]*br;
        VR[s] = pk2(nar, nbr); VI[s] = pk2(nai, nbi);
    }
}

// packed gate on lane bit j (shfl butterfly)
__device__ __forceinline__ void lgateP(u64* VR, u64* VI, const float* __restrict__ u,
                                       int lane, int j) {
    const int hi = (lane >> j) & 1;
    const float car = hi ? u[6] : u[0], cai = hi ? u[7] : u[1];
    const float cbr = hi ? u[4] : u[2], cbi = hi ? u[5] : u[3];
    const u64 CAR = bc2(car), CAI = bc2(cai), NAI = bc2(-cai);
    const u64 CBR = bc2(cbr), CBI = bc2(cbi), NBI = bc2(-cbi);
    #pragma unroll
    for (int s = 0; s < 8; ++s) {
        u64 pr = shfl2x(VR[s], 1 << j), pi = shfl2x(VI[s], 1 << j);
        u64 nr = f2fma(NBI, pi, f2fma(CBR, pr, f2fma(NAI, VI[s], f2mul(CAR, VR[s]))));
        u64 ni = f2fma(CBI, pr, f2fma(CBR, pi, f2fma(CAI, VR[s], f2mul(CAR, VI[s]))));
        VR[s] = nr; VI[s] = ni;
    }
}

// in-place pass-B permutation of 16 slots across lanes (cycle-following).
__device__ __forceinline__ void perm16(float* v, int se0, int so0, int se1, int so1) {
    const unsigned M = 0xffffffffu; float t;
    v[0] = __shfl_sync(M, v[0], se0);
    v[1] = __shfl_sync(M, v[1], so0);
    t = v[2]; v[2] = __shfl_sync(M, v[3], se0); v[3] = __shfl_sync(M, t, so0);
    t = v[4]; v[4] = __shfl_sync(M, v[6], se0); v[6] = __shfl_sync(M, v[5], se0);
              v[5] = __shfl_sync(M, v[7], so0); v[7] = __shfl_sync(M, t, so0);
    t = v[8];  v[8]  = __shfl_sync(M, v[12], se1); v[12] = __shfl_sync(M, v[10], se1);
               v[10] = __shfl_sync(M, v[15], se1); v[15] = __shfl_sync(M, t, so1);
    t = v[9];  v[9]  = __shfl_sync(M, v[13], so1); v[13] = __shfl_sync(M, v[11], so1);
               v[11] = __shfl_sync(M, v[14], so1); v[14] = __shfl_sync(M, t, se1);
}

// ---------------------------------------------------------------------------
// Pass A: lanes = bits 0..4, c3 = bits 5..7 (grid).
// Stage1: warp w = bits 12..15, slots = bits 8..11 (pack bit = 11).
// Stage2 (after SMEM exchange): warp w = bits 8..11, slots = bits 12..15
//        (pack bit = 15). Perm sfx8 on bits 8..15 folded into store address.
// ---------------------------------------------------------------------------
__global__ void __launch_bounds__(TPB, 2) kA(const float* __restrict__ x,
                                             const float* __restrict__ par,
                                             int layer, int first) {
    extern __shared__ float2 buf[];               // [e8][e12][lane] = 8192 float2
    float* aux = (float*)(buf + 8192);
    float* gU  = aux;         // 64
    float* csn = aux + 64;    // 32
    float* tL  = aux + 96;    // 32
    float* t8  = aux + 128;   // 16
    float* t12 = aux + 144;   // 16

    const int tid = threadIdx.x, lane = tid & 31, w = tid >> 5;
    const int c3  = blockIdx.x;
    const unsigned base = (unsigned)blockIdx.y << 16;

    if (tid < 8) compute_gate(par, layer, 7 - tid, gU + tid * 8);  // bit 8+j -> cq 7-j

    u64 VR[8], VI[8];

    if (first) {
        if (tid < 16) {
            float s, c; sincosf(0.5f * x[blockIdx.y * 16 + (15 - tid)], &s, &c);
            csn[tid] = c; csn[16 + tid] = s;
        }
        __syncthreads();
        if (tid < 32) {
            float p = 1.f;
            #pragma unroll
            for (int j = 0; j < 5; ++j) p *= ((tid >> j) & 1) ? csn[16 + j] : csn[j];
            #pragma unroll
            for (int j = 5; j < 8; ++j) p *= ((c3 >> (j - 5)) & 1) ? csn[16 + j] : csn[j];
            tL[tid] = p;
        } else if (tid < 48) {
            int e = tid - 32; float p = 1.f;
            #pragma unroll
            for (int j = 0; j < 4; ++j) p *= ((e >> j) & 1) ? csn[16 + 8 + j] : csn[8 + j];
            t8[e] = p;
        } else if (tid < 64) {
            int e = tid - 48; float p = 1.f;
            #pragma unroll
            for (int j = 0; j < 4; ++j) p *= ((e >> j) & 1) ? csn[16 + 12 + j] : csn[12 + j];
            t12[e] = p;
        }
        __syncthreads();
        const int pcBase = __popc((unsigned)lane) + __popc((unsigned)c3) + __popc((unsigned)w);
        const float mw = t12[w] * tL[lane];
        #pragma unroll
        for (int k = 0; k < 8; ++k) {
            float r[2], i2[2];
            #pragma unroll
            for (int h = 0; h < 2; ++h) {
                int e8 = (h << 3) | k;
                float m = mw * t8[e8];
                int pc = (pcBase + __popc((unsigned)e8)) & 3;
                float re = 0.f, im = 0.f;
                if (pc == 0) re = m; else if (pc == 1) im = -m;
                else if (pc == 2) re = -m; else im = m;
                r[h] = re; i2[h] = im;
            }
            VR[k] = pk2(r[0], r[1]); VI[k] = pk2(i2[0], i2[1]);
        }
    } else {
        #pragma unroll
        for (int k = 0; k < 8; ++k) {
            unsigned g0 = base | (w << 12) | (k << 8) | (c3 << 5) | lane;
            float ar, ai, br, bi;
            ld_h2(&g_st[g0], ar, ai);
            ld_h2(&g_st[g0 | (8u << 8)], br, bi);
            VR[k] = pk2(ar, br); VI[k] = pk2(ai, bi);
        }
    }
    __syncthreads();                               // gU (and tables) visible

    // stage1: gates on bits 8,9,10 (slot bits) + bit 11 (pack bit)
    rgateP<1>(VR, VI, gU + 0);
    rgateP<2>(VR, VI, gU + 8);
    rgateP<4>(VR, VI, gU + 16);
    pgateP(VR, VI, gU + 24);

    // exchange: buf[e8][e12=w][lane]
    #pragma unroll
    for (int k = 0; k < 8; ++k) {
        float r0, r1, i0, i1;
        upk2(VR[k], r0, r1); upk2(VI[k], i0, i1);
        buf[(k * 16 + w) * 32 + lane]       = make_float2(r0, i0);
        buf[((8 | k) * 16 + w) * 32 + lane] = make_float2(r1, i1);
    }
    __syncthreads();
    #pragma unroll
    for (int k = 0; k < 8; ++k) {
        float2 a = buf[(w * 16 + k) * 32 + lane];        // e8=w, e12=k
        float2 b = buf[(w * 16 + (8 | k)) * 32 + lane];  // e12=8|k
        VR[k] = pk2(a.x, b.x); VI[k] = pk2(a.y, b.y);
    }

    // stage2: gates on bits 12,13,14 (slot bits) + bit 15 (pack bit)
    rgateP<1>(VR, VI, gU + 32);
    rgateP<2>(VR, VI, gU + 40);
    rgateP<4>(VR, VI, gU + 48);
    pgateP(VR, VI, gU + 56);

    // store with sfx8 perm folded in: d12 = sfx4(e12), d8 = sfx4(w) ^ (par(e12)?15:0)
    int sw = w ^ (w >> 1); sw ^= (sw >> 2);
    const int dwA = sw, dwB = sw ^ 15;
    #pragma unroll
    for (int k = 0; k < 8; ++k) {
        float r0, r1, i0, i1;
        upk2(VR[k], r0, r1); upk2(VI[k], i0, i1);
        #pragma unroll
        for (int h = 0; h < 2; ++h) {
            int e12 = (h << 3) | k;
            int d12 = e12 ^ (e12 >> 1); d12 ^= (d12 >> 2);
            int dw  = (__popc((unsigned)e12) & 1) ? dwB : dwA;
            unsigned g = base | (d12 << 12) | (dw << 8) | (c3 << 5) | lane;
            st_h2(&g_st[g], h ? r1 : r0, h ? i1 : i0);
        }
    }
}

// ---------------------------------------------------------------------------
// Pass B shared pieces: lane = bits 0..4, slot k = bits 5..7, pack = b8,
// warp: b15 = w>>3, w9 = w&7 -> bits 9..11, cc = bits 12..14 (grid).
// ---------------------------------------------------------------------------
__device__ __forceinline__ void b_load_gates(float* re, float* im,
                                             unsigned base, int b15, int cc,
                                             int w9, int lane, const float* gU) {
    u64 VR[8], VI[8];
    #pragma unroll
    for (int k = 0; k < 8; ++k) {
        unsigned g0 = base | ((unsigned)b15 << 15) | (cc << 12) | (w9 << 9)
                    | (k << 5) | lane;
        float ar, ai, br, bi;
        ld_h2(&g_st[g0], ar, ai);
        ld_h2(&g_st[g0 | 256u], br, bi);
        VR[k] = pk2(ar, br); VI[k] = pk2(ai, bi);
    }
    __syncthreads();                     // gU visible
    rgateP<1>(VR, VI, gU + 5 * 8);
    rgateP<2>(VR, VI, gU + 6 * 8);
    rgateP<4>(VR, VI, gU + 7 * 8);
    #pragma unroll
    for (int j = 0; j < 5; ++j) lgateP(VR, VI, gU + j * 8, lane, j);
    #pragma unroll
    for (int k = 0; k < 8; ++k) {
        upk2(VR[k], re[k], re[8 | k]);
        upk2(VI[k], im[k], im[8 | k]);
    }
}

__device__ __forceinline__ void lane_variants(int lane, int& se0, int& so0,
                                              int& se1, int& so1) {
    se0 = (lane ^ (lane >> 1)) & 31;
    so0 = se0 ^ 16;
    int u1e = lane ^ 63; se1 = (u1e ^ (u1e >> 1)) & 31;
    int u1o = lane ^ 31; so1 = (u1o ^ (u1o >> 1)) & 31;
}

__global__ void __launch_bounds__(TPB, 2) kBmid(const float* __restrict__ par, int layer) {
    __shared__ float  gU[64];
    __shared__ float2 xbuf[2][8][16][16];

    const int tid = threadIdx.x, lane = tid & 31, w = tid >> 5;
    const int b15 = w >> 3, w9 = w & 7;
    const int cc  = blockIdx.x;
    const unsigned base = (unsigned)blockIdx.y << 16;

    if (tid < 8) compute_gate(par, layer, 15 - tid, gU + tid * 8);  // gU[q]: bit q

    float re[16], im[16];
    b_load_gates(re, im, base, b15, cc, w9, lane, gU);

    int se0, so0, se1, so1; lane_variants(lane, se0, so0, se1, so1);
    perm16(re, se0, so0, se1, so1);
    perm16(im, se0, so0, se1, so1);

    // b15 flip for odd dest lanes: swap with partner warp (w ^ 8)
    if (lane & 1) {
        #pragma unroll
        for (int s = 0; s < 16; ++s)
            xbuf[b15][w9][s][lane >> 1] = make_float2(re[s], im[s]);
    }
    __syncthreads();
    if (lane & 1) {
        #pragma unroll
        for (int s = 0; s < 16; ++s) {
            float2 v = xbuf[b15 ^ 1][w9][s][lane >> 1];
            re[s] = v.x; im[s] = v.y;
        }
    }

    #pragma unroll
    for (int s = 0; s < 16; ++s) {
        unsigned g = base | ((unsigned)b15 << 15) | (cc << 12) | (w9 << 9)
                   | ((s >> 3) << 8) | ((s & 7) << 5) | lane;
        st_h2(&g_st[g], re[s], im[s]);
    }
}

// ---------------------------------------------------------------------------
// Final pass B: Walsh-tree <Z> partials, no state store.
// ---------------------------------------------------------------------------
__global__ void __launch_bounds__(TPB, 2) kBlast(const float* __restrict__ par, int layer) {
    __shared__ float gU[64];
    __shared__ float red[16][17];

    const int tid = threadIdx.x, lane = tid & 31, w = tid >> 5;
    const int b15 = w >> 3, w9 = w & 7;
    const int cc  = blockIdx.x;
    const unsigned base = (unsigned)blockIdx.y << 16;

    if (tid < 8) compute_gate(par, layer, 15 - tid, gU + tid * 8);

    float re[16], im[16];
    b_load_gates(re, im, base, b15, cc, w9, lane, gU);

    int se0, so0, se1, so1; lane_variants(lane, se0, so0, se1, so1);
    perm16(re, se0, so0, se1, so1);
    perm16(im, se0, so0, se1, so1);

    float p[16];
    #pragma unroll
    for (int s = 0; s < 16; ++s) p[s] = re[s] * re[s] + im[s] * im[s];

    float ee[8], T8 = 0.f;
    #pragma unroll
    for (int k = 0; k < 8; ++k) { ee[k] = p[k] + p[k + 8]; T8 += p[k] - p[k + 8]; }
    float a0 = ee[0] + ee[4], a1 = ee[1] + ee[5], a2 = ee[2] + ee[6], a3 = ee[3] + ee[7];
    float T7 = (ee[0] - ee[4]) + (ee[1] - ee[5]) + (ee[2] - ee[6]) + (ee[3] - ee[7]);
    float c0 = a0 + a2, c1 = a1 + a3;
    float T6 = (a0 - a2) + (a1 - a3);
    float T0 = c0 + c1, T5 = c0 - c1;

    const int bitsv = ((b15 ^ (lane & 1)) << 15) | (cc << 12) | (w9 << 9) | lane;
    float acc[16];
    #pragma unroll
    for (int m = 0; m < 16; ++m) {
        if      (m == 5) acc[m] = T5;
        else if (m == 6) acc[m] = T6;
        else if (m == 7) acc[m] = T7;
        else if (m == 8) acc[m] = T8;
        else             acc[m] = ((bitsv >> m) & 1) ? -T0 : T0;
    }

    #pragma unroll
    for (int m = 0; m < 16; ++m) {
        float v = acc[m];
        #pragma unroll
        for (int o = 16; o > 0; o >>= 1) v += __shfl_xor_sync(0xffffffffu, v, o);
        if (lane == 0) red[m][w] = v;
    }
    __syncthreads();
    if (tid < 16) {
        float s = 0.f;
        #pragma unroll
        for (int k = 0; k < 16; ++k) s += red[tid][k];
        g_part[(blockIdx.y * 8 + cc) * 16 + tid] = s;
    }
}

__global__ void kBfin(float* __restrict__ out) {
    int i = blockIdx.x * blockDim.x + threadIdx.x;
    if (i < BAT * 16) {
        int b = i >> 4, m = i & 15;
        float s = 0.f;
        #pragma unroll
        for (int cc = 0; cc < 8; ++cc) s += g_part[(b * 8 + cc) * 16 + m];
        out[b * 16 + (15 - m)] = s;
    }
}

// ---------------------------------------------------------------------------
extern "C" void kernel_launch(void* const* d_in, const int* in_sizes, int n_in,
                              void* d_out, int out_size) {
    const float* x   = (const float*)d_in[0];
    const float* par = (const float*)d_in[1];
    if (n_in >= 2 && in_sizes[0] == 192) {
        const float* t = x; x = par; par = t;
    }
    float* out = (float*)d_out;

    const size_t smA = 8192 * sizeof(float2) + 160 * sizeof(float);
    cudaFuncSetAttribute(kA, cudaFuncAttributeMaxDynamicSharedMemorySize, (int)smA);

    dim3 grid8(8, BAT);
    for (int layer = 0; layer < 4; ++layer) {
        kA<<<grid8, TPB, smA>>>(x, par, layer, layer == 0 ? 1 : 0);
        if (layer < 3) {
            kBmid<<<grid8, TPB>>>(par, layer);
        } else {
            kBlast<<<grid8, TPB>>>(par, layer);
            kBfin<<<32, 256>>>(out);
        }
    }
}

// round 6
// speedup vs baseline: 2.4794x; 1.1997x over previous
#include <cuda_runtime.h>
#include <cuda_fp16.h>
#include <math.h>

// ---------------------------------------------------------------------------
// 16-qubit statevector, batch 512. circuit qubit i <-> index bit (15-i).
// Layer = 16 one-qubit gates + CNOT-ladder = suffix-XOR permutation.
// State between passes: __half2(re,im), fp32 compute (f32x2 packed FMA).
// Layer 0 pass A is ANALYTIC: state after RX-init + hi gates + hi perm is a
//   product state -> kB0 synthesizes its tile from two 256-entry tables.
// Pass A (layers 1..3): gates bits 8..15, two rgate stages + SMEM exchange,
//   hi perm folded into store address.
// Pass B: lane = bits 0..4, slots k = bits 5..7, pack = b15 (ungated),
//   warp w = bits 8..11. Gates = 3 rgateP + 5 lgateP. Ladder perm on bits
//   0..7 + b15-wrap folded into store: dense 128B blocks, halves swapped by d0.
// ---------------------------------------------------------------------------

#define TPB 512
#define BAT 512

typedef unsigned long long u64;

__device__ __half2 g_st[(size_t)BAT * 65536];
__device__ float   g_part[BAT * 8 * 16];

// ---------------- packed f32x2 helpers ----------------
__device__ __forceinline__ u64 pk2(float x, float y) {
    u64 r; asm("mov.b64 %0,{%1,%2};" : "=l"(r) : "f"(x), "f"(y)); return r;
}
__device__ __forceinline__ void upk2(u64 v, float& x, float& y) {
    asm("mov.b64 {%0,%1},%2;" : "=f"(x), "=f"(y) : "l"(v));
}
__device__ __forceinline__ u64 bc2(float x) { return pk2(x, x); }
__device__ __forceinline__ u64 f2mul(u64 a, u64 b) {
    u64 r; asm("mul.rn.f32x2 %0,%1,%2;" : "=l"(r) : "l"(a), "l"(b)); return r;
}
__device__ __forceinline__ u64 f2fma(u64 a, u64 b, u64 c) {
    u64 r; asm("fma.rn.f32x2 %0,%1,%2,%3;" : "=l"(r) : "l"(a), "l"(b), "l"(c)); return r;
}
__device__ __forceinline__ u64 shfl2x(u64 v, int m) {
    float x, y; upk2(v, x, y);
    x = __shfl_xor_sync(0xffffffffu, x, m);
    y = __shfl_xor_sync(0xffffffffu, y, m);
    return pk2(x, y);
}
__device__ __forceinline__ void ld_h2(const __half2* p, float& re, float& im) {
    float2 v = __half22float2(*p); re = v.x; im = v.y;
}
__device__ __forceinline__ void st_h2(__half2* p, float re, float im) {
    *p = __floats2half2_rn(re, im);
}
__device__ __forceinline__ float2 cmulf(float2 a, float2 b) {
    return make_float2(a.x * b.x - a.y * b.y, a.x * b.y + a.y * b.x);
}
__device__ __forceinline__ int sfx5(int v) {
    v ^= v >> 1; v ^= v >> 2; v ^= v >> 4; return v & 31;
}

// U = Ry(p2)*Rx(p1)*Rz(p0): u00r,u00i,u01r,u01i,u10r,u10i,u11r,u11i
__device__ __forceinline__ void compute_gate(const float* __restrict__ par,
                                             int layer, int cq, float* uo) {
    const float* pp = par + ((layer * 16 + cq) * 3);
    float sz, cz, sx, cx_, sy, cy;
    sincosf(0.5f * pp[0], &sz, &cz);
    sincosf(0.5f * pp[1], &sx, &cx_);
    sincosf(0.5f * pp[2], &sy, &cy);
    float M00r =  cx_ * cz, M00i = -cx_ * sz;
    float M01r =  sx  * sz, M01i = -sx  * cz;
    float M10r = -sx  * sz, M10i = -sx  * cz;
    float M11r =  cx_ * cz, M11i =  cx_ * sz;
    uo[0] = cy * M00r - sy * M10r;  uo[1] = cy * M00i - sy * M10i;
    uo[2] = cy * M01r - sy * M11r;  uo[3] = cy * M01i - sy * M11i;
    uo[4] = sy * M00r + cy * M10r;  uo[5] = sy * M00i + cy * M10i;
    uo[6] = sy * M01r + cy * M11r;  uo[7] = sy * M01i + cy * M11i;
}

// packed gate on slot bit B, pure f32x2
template<int B>
__device__ __forceinline__ void rgateP(u64* VR, u64* VI, const float* __restrict__ u) {
    const u64 U0 = bc2(u[0]), U1 = bc2(u[1]), N1 = bc2(-u[1]);
    const u64 U2 = bc2(u[2]), U3 = bc2(u[3]), N3 = bc2(-u[3]);
    const u64 U4 = bc2(u[4]), U5 = bc2(u[5]), N5 = bc2(-u[5]);
    const u64 U6 = bc2(u[6]), U7 = bc2(u[7]), N7 = bc2(-u[7]);
    #pragma unroll
    for (int s = 0; s < 8; ++s) if (!(s & B)) {
        u64 ar = VR[s], ai = VI[s], br = VR[s | B], bi = VI[s | B];
        VR[s]     = f2fma(N3, bi, f2fma(U2, br, f2fma(N1, ai, f2mul(U0, ar))));
        VI[s]     = f2fma(U3, br, f2fma(U2, bi, f2fma(U1, ar, f2mul(U0, ai))));
        VR[s | B] = f2fma(N7, bi, f2fma(U6, br, f2fma(N5, ai, f2mul(U4, ar))));
        VI[s | B] = f2fma(U7, br, f2fma(U6, bi, f2fma(U5, ar, f2mul(U4, ai))));
    }
}

// gate on the pack bit itself, scalar
__device__ __forceinline__ void pgateP(u64* VR, u64* VI, const float* __restrict__ u) {
    #pragma unroll
    for (int s = 0; s < 8; ++s) {
        float ar, br, ai, bi;
        upk2(VR[s], ar, br); upk2(VI[s], ai, bi);
        float nar = u[0]*ar - u[1]*ai + u[2]*br - u[3]*bi;
        float nai = u[0]*ai + u[1]*ar + u[2]*bi + u[3]*br;
        float nbr = u[4]*ar - u[5]*ai + u[6]*br - u[7]*bi;
        float nbi = u[4]*ai + u[5]*ar + u[6]*bi + u[7]*br;
        VR[s] = pk2(nar, nbr); VI[s] = pk2(nai, nbi);
    }
}

// packed gate on lane bit j (shfl butterfly)
__device__ __forceinline__ void lgateP(u64* VR, u64* VI, const float* __restrict__ u,
                                       int lane, int j) {
    const int hi = (lane >> j) & 1;
    const float car = hi ? u[6] : u[0], cai = hi ? u[7] : u[1];
    const float cbr = hi ? u[4] : u[2], cbi = hi ? u[5] : u[3];
    const u64 CAR = bc2(car), CAI = bc2(cai), NAI = bc2(-cai);
    const u64 CBR = bc2(cbr), CBI = bc2(cbi), NBI = bc2(-cbi);
    #pragma unroll
    for (int s = 0; s < 8; ++s) {
        u64 pr = shfl2x(VR[s], 1 << j), pi = shfl2x(VI[s], 1 << j);
        u64 nr = f2fma(NBI, pi, f2fma(CBR, pr, f2fma(NAI, VI[s], f2mul(CAR, VR[s]))));
        u64 ni = f2fma(CBI, pr, f2fma(CBR, pi, f2fma(CAI, VR[s], f2mul(CAR, VI[s]))));
        VR[s] = nr; VI[s] = ni;
    }
}

// pass-B gates: rgate bits 5,6,7 + lgate bits 0..4 (pack = b15, never gated)
__device__ __forceinline__ void kb_gates(u64* VR, u64* VI, const float* gU, int lane) {
    rgateP<1>(VR, VI, gU + 40);
    rgateP<2>(VR, VI, gU + 48);
    rgateP<4>(VR, VI, gU + 56);
    #pragma unroll
    for (int j = 0; j < 5; ++j) lgateP(VR, VI, gU + j * 8, lane, j);
}

// pass-B store with full ladder perm folded in.
// dest low8 d = sfx8((k<<5)|lane) ^ (b8?255:0); b15' = b15 ^ d0.
__device__ __forceinline__ void kb_store(u64* VR, u64* VI, unsigned base,
                                         int cc, int w, int lane) {
    const int b8 = w & 1;
    const int S  = sfx5(lane);
    const int pl = __popc((unsigned)lane) & 1;
    #pragma unroll
    for (int k = 0; k < 8; ++k) {
        const int pk  = __popc((unsigned)k) & 1;                 // compile-time
        const int s3  = (k ^ (k >> 1) ^ (k >> 2)) & 7;           // sfx3(k), ct
        int flip = pk ^ b8;                                      // warp-uniform
        int dlo  = S ^ (flip ? 31 : 0);
        int dh3  = s3 ^ (b8 ? 7 : 0);
        int d0   = pl ^ flip;                                    // per lane
        float r0, r1, i0, i1;
        upk2(VR[k], r0, r1); upk2(VI[k], i0, i1);
        float Ar = d0 ? r1 : r0, Ai = d0 ? i1 : i0;              // dest b15'=0
        float Br = d0 ? r0 : r1, Bi = d0 ? i0 : i1;              // dest b15'=1
        unsigned a = base | (cc << 12) | (w << 8) | (dh3 << 5) | dlo;
        st_h2(&g_st[a], Ar, Ai);
        st_h2(&g_st[a | 0x8000u], Br, Bi);
    }
}

// ---------------------------------------------------------------------------
// Pass A (layers 1..3): lanes = bits 0..4, c3 = bits 5..7 (grid).
// Stage1: warp w = bits 12..15, slots = bits 8..10, pack = bit 11.
// Stage2 (after SMEM exchange): slots = bits 12..14, pack = bit 15.
// sfx8 perm on bits 8..15 folded into store address.
// ---------------------------------------------------------------------------
__global__ void __launch_bounds__(TPB, 2) kA(const float* __restrict__ par, int layer) {
    extern __shared__ float2 buf[];               // 8192 float2 = 64KB
    float* gU = (float*)(buf + 8192);             // 64 floats

    const int tid = threadIdx.x, lane = tid & 31, w = tid >> 5;
    const int c3  = blockIdx.x;
    const unsigned base = (unsigned)blockIdx.y << 16;

    if (tid < 8) compute_gate(par, layer, 7 - tid, gU + tid * 8);  // bit 8+j -> cq 7-j

    u64 VR[8], VI[8];
    #pragma unroll
    for (int k = 0; k < 8; ++k) {
        unsigned g0 = base | (w << 12) | (k << 8) | (c3 << 5) | lane;
        float ar, ai, br, bi;
        ld_h2(&g_st[g0], ar, ai);
        ld_h2(&g_st[g0 | (8u << 8)], br, bi);
        VR[k] = pk2(ar, br); VI[k] = pk2(ai, bi);
    }
    __syncthreads();                               // gU visible

    // stage1: gates bits 8,9,10 (slots) + 11 (pack)
    rgateP<1>(VR, VI, gU + 0);
    rgateP<2>(VR, VI, gU + 8);
    rgateP<4>(VR, VI, gU + 16);
    pgateP(VR, VI, gU + 24);

    // exchange: buf[e8][e12=w][lane]
    #pragma unroll
    for (int k = 0; k < 8; ++k) {
        float r0, r1, i0, i1;
        upk2(VR[k], r0, r1); upk2(VI[k], i0, i1);
        buf[(k * 16 + w) * 32 + lane]       = make_float2(r0, i0);
        buf[((8 | k) * 16 + w) * 32 + lane] = make_float2(r1, i1);
    }
    __syncthreads();
    #pragma unroll
    for (int k = 0; k < 8; ++k) {
        float2 a = buf[(w * 16 + k) * 32 + lane];        // e8=w, e12=k
        float2 b = buf[(w * 16 + (8 | k)) * 32 + lane];  // e12=8|k
        VR[k] = pk2(a.x, b.x); VI[k] = pk2(a.y, b.y);
    }

    // stage2: gates bits 12,13,14 (slots) + 15 (pack)
    rgateP<1>(VR, VI, gU + 32);
    rgateP<2>(VR, VI, gU + 40);
    rgateP<4>(VR, VI, gU + 48);
    pgateP(VR, VI, gU + 56);

    // store with sfx8 perm on hi bits folded in
    int sw = w ^ (w >> 1); sw ^= (sw >> 2);
    const int dwA = sw, dwB = sw ^ 15;
    #pragma unroll
    for (int k = 0; k < 8; ++k) {
        float r0, r1, i0, i1;
        upk2(VR[k], r0, r1); upk2(VI[k], i0, i1);
        #pragma unroll
        for (int h = 0; h < 2; ++h) {
            int e12 = (h << 3) | k;
            int d12 = e12 ^ (e12 >> 1); d12 ^= (d12 >> 2);
            int dw  = (__popc((unsigned)e12) & 1) ? dwB : dwA;
            unsigned g = base | (d12 << 12) | (dw << 8) | (c3 << 5) | lane;
            st_h2(&g_st[g], h ? r1 : r0, h ? i1 : i0);
        }
    }
}

// ---------------------------------------------------------------------------
// kB0 (layer 0): synthesize state (product state after RX init + layer-0 hi
// gates + hi perm) from tables, then layer-0 lo gates + perm + store.
// ---------------------------------------------------------------------------
__global__ void __launch_bounds__(TPB, 2) kB0(const float* __restrict__ x,
                                              const float* __restrict__ par) {
    __shared__ float4 fv[16];      // per-qubit 2-vec factors (complex pairs)
    __shared__ float  gU[64];
    __shared__ float2 Tlo[256], Thi[256];

    const int tid = threadIdx.x, lane = tid & 31, w = tid >> 5;  // w = bits 8..11
    const int cc  = blockIdx.x;
    const unsigned base = (unsigned)blockIdx.y << 16;

    if (tid < 16) {
        int m = tid;                         // index bit m <-> cq 15-m
        float s, c; sincosf(0.5f * x[blockIdx.y * 16 + (15 - m)], &s, &c);
        if (m < 8) {
            fv[m] = make_float4(c, 0.f, 0.f, -s);          // RX|0> = (c, -i s)
        } else {
            float U[8]; compute_gate(par, 0, 15 - m, U);   // layer-0 hi gate
            fv[m] = make_float4(U[0]*c + U[3]*s, U[1]*c - U[2]*s,
                                U[4]*c + U[7]*s, U[5]*c - U[6]*s);
        }
    } else if (tid >= 32 && tid < 40) {
        compute_gate(par, 0, 15 - (tid - 32), gU + (tid - 32) * 8);  // lo gates
    }
    __syncthreads();

    {   // build tables: threads 0..255 -> Tlo, 256..511 -> Thi (perm-relabeled)
        int e = tid & 255;
        int mbase = (tid < 256) ? 0 : 8;
        float2 cacc = make_float2(1.f, 0.f);
        #pragma unroll
        for (int m = 0; m < 8; ++m) {
            float4 F = fv[mbase + m];
            float2 b = ((e >> m) & 1) ? make_float2(F.z, F.w)
                                      : make_float2(F.x, F.y);
            cacc = cmulf(cacc, b);
        }
        if (tid < 256) {
            Tlo[e] = cacc;
        } else {
            int d = e ^ (e >> 1); d ^= d >> 2; d ^= d >> 4;   // sfx8(e)
            Thi[d & 255] = cacc;                              // Thi[h]=F(inv(h))
        }
    }
    __syncthreads();

    u64 VR[8], VI[8];
    float2 H0 = Thi[w | (cc << 4)];
    float2 H1 = Thi[w | (cc << 4) | 128];
    #pragma unroll
    for (int k = 0; k < 8; ++k) {
        float2 L  = Tlo[(k << 5) | lane];
        float2 a0 = cmulf(H0, L), a1 = cmulf(H1, L);
        VR[k] = pk2(a0.x, a1.x); VI[k] = pk2(a0.y, a1.y);
    }

    kb_gates(VR, VI, gU, lane);
    kb_store(VR, VI, base, cc, w, lane);
}

// ---------------------------------------------------------------------------
// kBmid (layers 1,2): load, lo gates, perm-folded store.
// ---------------------------------------------------------------------------
__global__ void __launch_bounds__(TPB, 2) kBmid(const float* __restrict__ par, int layer) {
    __shared__ float gU[64];

    const int tid = threadIdx.x, lane = tid & 31, w = tid >> 5;
    const int cc  = blockIdx.x;
    const unsigned base = (unsigned)blockIdx.y << 16;

    if (tid < 8) compute_gate(par, layer, 15 - tid, gU + tid * 8);

    u64 VR[8], VI[8];
    #pragma unroll
    for (int k = 0; k < 8; ++k) {
        unsigned a = base | (cc << 12) | (w << 8) | (k << 5) | lane;
        float r0, i0, r1, i1;
        ld_h2(&g_st[a], r0, i0);
        ld_h2(&g_st[a | 0x8000u], r1, i1);
        VR[k] = pk2(r0, r1); VI[k] = pk2(i0, i1);
    }
    __syncthreads();

    kb_gates(VR, VI, gU, lane);
    kb_store(VR, VI, base, cc, w, lane);
}

// ---------------------------------------------------------------------------
// kBlast (layer 3): lo gates, then <Z> partials with perm folded analytically.
// ---------------------------------------------------------------------------
__global__ void __launch_bounds__(TPB, 2) kBlast(const float* __restrict__ par, int layer) {
    __shared__ float gU[64];
    __shared__ float red[16][17];

    const int tid = threadIdx.x, lane = tid & 31, w = tid >> 5;
    const int cc  = blockIdx.x;
    const unsigned base = (unsigned)blockIdx.y << 16;
    const int b8 = w & 1;

    if (tid < 8) compute_gate(par, layer, 15 - tid, gU + tid * 8);

    u64 VR[8], VI[8];
    #pragma unroll
    for (int k = 0; k < 8; ++k) {
        unsigned a = base | (cc << 12) | (w << 8) | (k << 5) | lane;
        float r0, i0, r1, i1;
        ld_h2(&g_st[a], r0, i0);
        ld_h2(&g_st[a | 0x8000u], r1, i1);
        VR[k] = pk2(r0, r1); VI[k] = pk2(i0, i1);
    }
    __syncthreads();

    kb_gates(VR, VI, gU, lane);

    // probabilities; ee indexed by j0 = sfx3(k) (ct); W0 with (-1)^par(k)
    float ee[8], W0 = 0.f;
    #pragma unroll
    for (int k = 0; k < 8; ++k) {
        const int j0 = (k ^ (k >> 1) ^ (k >> 2)) & 7;
        const int pk = __popc((unsigned)k) & 1;
        float r0, r1, i0, i1;
        upk2(VR[k], r0, r1); upk2(VI[k], i0, i1);
        float p0 = r0 * r0 + i0 * i0, p1 = r1 * r1 + i1 * i1;
        ee[j0] = p0 + p1;
        W0 += pk ? (p1 - p0) : (p0 - p1);
    }
    // Walsh tree over ee (dest bits 5..7, pre b8-relabel)
    float e04 = ee[0] + ee[4], e15 = ee[1] + ee[5];
    float e26 = ee[2] + ee[6], e37 = ee[3] + ee[7];
    float T7 = (ee[0] - ee[4]) + (ee[1] - ee[5]) + (ee[2] - ee[6]) + (ee[3] - ee[7]);
    float a0 = e04 + e26, a1 = e15 + e37;
    float T6 = (e04 - e26) + (e15 - e37);
    float T0 = a0 + a1, T5 = a0 - a1;
    if (b8) { T5 = -T5; T6 = -T6; T7 = -T7; W0 = -W0; }  // j -> j^7, sign flip

    const int S  = sfx5(lane);
    const int pl = __popc((unsigned)lane) & 1;
    float acc[16];
    #pragma unroll
    for (int m = 0; m < 16; ++m) {
        if      (m < 5)   acc[m] = ((S >> m) & 1) ? -T5 : T5;
        else if (m == 5)  acc[m] = T5;
        else if (m == 6)  acc[m] = T6;
        else if (m == 7)  acc[m] = T7;
        else if (m < 12)  acc[m] = ((w >> (m - 8)) & 1) ? -T0 : T0;
        else if (m < 15)  acc[m] = ((cc >> (m - 12)) & 1) ? -T0 : T0;
        else              acc[m] = pl ? -W0 : W0;
    }

    #pragma unroll
    for (int m = 0; m < 16; ++m) {
        float v = acc[m];
        #pragma unroll
        for (int o = 16; o > 0; o >>= 1) v += __shfl_xor_sync(0xffffffffu, v, o);
        if (lane == 0) red[m][w] = v;
    }
    __syncthreads();
    if (tid < 16) {
        float s = 0.f;
        #pragma unroll
        for (int k = 0; k < 16; ++k) s += red[tid][k];
        g_part[(blockIdx.y * 8 + cc) * 16 + tid] = s;
    }
}

__global__ void kBfin(float* __restrict__ out) {
    int i = blockIdx.x * blockDim.x + threadIdx.x;
    if (i < BAT * 16) {
        int b = i >> 4, m = i & 15;
        float s = 0.f;
        #pragma unroll
        for (int cc = 0; cc < 8; ++cc) s += g_part[(b * 8 + cc) * 16 + m];
        out[b * 16 + (15 - m)] = s;
    }
}

// ---------------------------------------------------------------------------
extern "C" void kernel_launch(void* const* d_in, const int* in_sizes, int n_in,
                              void* d_out, int out_size) {
    const float* x   = (const float*)d_in[0];
    const float* par = (const float*)d_in[1];
    if (n_in >= 2 && in_sizes[0] == 192) {
        const float* t = x; x = par; par = t;
    }
    float* out = (float*)d_out;

    const size_t smA = 8192 * sizeof(float2) + 64 * sizeof(float);
    cudaFuncSetAttribute(kA, cudaFuncAttributeMaxDynamicSharedMemorySize, (int)smA);

    dim3 grid8(8, BAT);
    kB0<<<grid8, TPB>>>(x, par);                       // layer 0 (A analytic + B)
    for (int layer = 1; layer < 4; ++layer) {
        kA<<<grid8, TPB, smA>>>(par, layer);
        if (layer < 3) {
            kBmid<<<grid8, TPB>>>(par, layer);
        } else {
            kBlast<<<grid8, TPB>>>(par, layer);
            kBfin<<<32, 256>>>(out);
        }
    }
}